// round 7
// baseline (speedup 1.0000x reference)
#include <cuda_runtime.h>
#include <cuda_bf16.h>
#include <cstdint>
#include <cstddef>

// ---------------------------------------------------------------------------
// LSTM_87351044866551  (Round 7)
//   P: transpose+split Wi -> g_wb_hi/lo bf16 [N=512][K=2048]
//   G: xg = x@Wi, HMMA 3-term bf16 split, 512 thr, 3-stage cp.async ring
//   L: LSTM recurrence v4: packed fma.rn.f32x2 (FFMA2), k-pair accumulation
// ---------------------------------------------------------------------------

#define M_DIM 32768
#define N_DIM 512
#define K_DIM 2048

__device__ float g_xg[(size_t)M_DIM * N_DIM];            // 64 MB scratch
__device__ __align__(256) __nv_bfloat16 g_wb_hi[(size_t)N_DIM * K_DIM];
__device__ __align__(256) __nv_bfloat16 g_wb_lo[(size_t)N_DIM * K_DIM];

// ===========================================================================
// helpers (base ISA only — tcgen05 not assemblable on this harness)
// ===========================================================================
__device__ __forceinline__ uint32_t smem_u32(const void* p) {
    uint32_t a;
    asm("{ .reg .u64 t; cvta.to.shared.u64 t, %1; cvt.u32.u64 %0, t; }"
        : "=r"(a) : "l"(p));
    return a;
}
__device__ __forceinline__ void ldsm_x4(uint32_t& r0, uint32_t& r1,
                                        uint32_t& r2, uint32_t& r3,
                                        uint32_t addr) {
    asm volatile("ldmatrix.sync.aligned.m8n8.x4.shared.b16 {%0,%1,%2,%3},[%4];"
                 : "=r"(r0), "=r"(r1), "=r"(r2), "=r"(r3) : "r"(addr));
}
__device__ __forceinline__ void mma_bf16(float* d, const uint32_t* a,
                                         uint32_t b0, uint32_t b1) {
    asm volatile(
        "mma.sync.aligned.m16n8k16.row.col.f32.bf16.bf16.f32 "
        "{%0,%1,%2,%3},{%4,%5,%6,%7},{%8,%9},{%0,%1,%2,%3};"
        : "+f"(d[0]), "+f"(d[1]), "+f"(d[2]), "+f"(d[3])
        : "r"(a[0]), "r"(a[1]), "r"(a[2]), "r"(a[3]), "r"(b0), "r"(b1));
}
#define CPASYNC16(dst, src) \
    asm volatile("cp.async.cg.shared.global [%0],[%1],16;" :: "r"(dst), "l"(src))
#define CPCOMMIT() asm volatile("cp.async.commit_group;" ::: "memory")
#define CPWAIT1()  asm volatile("cp.async.wait_group 1;" ::: "memory")

// packed dual-fp32 FMA: d = a*b + d (lanewise) — emits FFMA2
__device__ __forceinline__ void ffma2(unsigned long long& d,
                                      unsigned long long a,
                                      unsigned long long b) {
    asm("fma.rn.f32x2 %0, %1, %2, %0;" : "+l"(d) : "l"(a), "l"(b));
}
__device__ __forceinline__ float f2_sum(unsigned long long d) {
    float lo, hi;
    asm("mov.b64 {%0,%1}, %2;" : "=f"(lo), "=f"(hi) : "l"(d));
    return lo + hi;
}

// ===========================================================================
// Kernel P: Wb_hi/lo[n][k] = split(Wi[k][n])
// ===========================================================================
__global__ __launch_bounds__(1024) void prep_w(const float* __restrict__ Wi) {
    __shared__ float t[32][33];
    const int k = blockIdx.x * 32 + threadIdx.y;
    const int n = blockIdx.y * 32 + threadIdx.x;
    t[threadIdx.y][threadIdx.x] = Wi[(size_t)k * N_DIM + n];
    __syncthreads();
    const int n2 = blockIdx.y * 32 + threadIdx.y;
    const int k2 = blockIdx.x * 32 + threadIdx.x;
    const float v = t[threadIdx.x][threadIdx.y];
    const __nv_bfloat16 h = __float2bfloat16_rn(v);
    const __nv_bfloat16 l = __float2bfloat16_rn(v - __bfloat162float(h));
    g_wb_hi[(size_t)n2 * K_DIM + k2] = h;
    g_wb_lo[(size_t)n2 * K_DIM + k2] = l;
}

// ===========================================================================
// Kernel G: HMMA GEMM, CTA 128x256, 512 thr, warp 32x64, K-chunk 32, 3-stage
// Stage (bytes): Ahi@0 (128x80), Alo@10240, Bhi@20480 (256x80), Blo@40960
// ===========================================================================
#define SROWB 80
#define A_LO_OFF 10240
#define B_HI_OFF 20480
#define B_LO_OFF 40960
#define STAGE_BYTES 61440
#define GEMM_SMEM (3 * STAGE_BYTES)
#define NCHUNK 64

__global__ __launch_bounds__(512, 1) void gemm_hmma(const float* __restrict__ x) {
    extern __shared__ __nv_bfloat16 smb[];
    const uint32_t sbase = smem_u32(smb);
    const int tid  = threadIdx.x;
    const int lane = tid & 31;
    const int w    = tid >> 5;
    const int wm   = w & 3;
    const int wn   = w >> 2;
    const int m0   = blockIdx.y * 128;
    const int n0   = blockIdx.x * 256;

    float acc[2][8][4];
#pragma unroll
    for (int a = 0; a < 2; a++)
#pragma unroll
        for (int b = 0; b < 8; b++)
#pragma unroll
            for (int c = 0; c < 4; c++) acc[a][b][c] = 0.f;

    const float* xA = x + (size_t)m0 * K_DIM;
    const __nv_bfloat16* bH = g_wb_hi + (size_t)n0 * K_DIM;
    const __nv_bfloat16* bL = g_wb_lo + (size_t)n0 * K_DIM;

    float4 av[2];

#define LDG_A(kt)                                                              \
    do {                                                                       \
        _Pragma("unroll")                                                      \
        for (int i = 0; i < 2; i++) {                                          \
            const int idx = tid + i * 512;                                     \
            const int r = idx >> 3, f4 = idx & 7;                              \
            av[i] = *(const float4*)(xA + (size_t)r * K_DIM + (kt) * 32 + f4 * 4); \
        }                                                                      \
    } while (0)

#define STS_A(s)                                                               \
    do {                                                                       \
        _Pragma("unroll")                                                      \
        for (int i = 0; i < 2; i++) {                                          \
            const int idx = tid + i * 512;                                     \
            const int r = idx >> 3, f4 = idx & 7;                              \
            const float4 v = av[i];                                            \
            __nv_bfloat16 hx = __float2bfloat16_rn(v.x);                       \
            __nv_bfloat16 hy = __float2bfloat16_rn(v.y);                       \
            __nv_bfloat16 hz = __float2bfloat16_rn(v.z);                       \
            __nv_bfloat16 hw = __float2bfloat16_rn(v.w);                       \
            __nv_bfloat16 lx = __float2bfloat16_rn(v.x - __bfloat162float(hx)); \
            __nv_bfloat16 ly = __float2bfloat16_rn(v.y - __bfloat162float(hy)); \
            __nv_bfloat16 lz = __float2bfloat16_rn(v.z - __bfloat162float(hz)); \
            __nv_bfloat16 lw = __float2bfloat16_rn(v.w - __bfloat162float(hw)); \
            __nv_bfloat162 h01, h23, l01, l23;                                 \
            h01.x = hx; h01.y = hy; h23.x = hz; h23.y = hw;                    \
            l01.x = lx; l01.y = ly; l23.x = lz; l23.y = lw;                    \
            uint2 hp, lp;                                                      \
            hp.x = *(uint32_t*)&h01; hp.y = *(uint32_t*)&h23;                  \
            lp.x = *(uint32_t*)&l01; lp.y = *(uint32_t*)&l23;                  \
            char* base = (char*)smb + (s) * STAGE_BYTES + r * SROWB + f4 * 8;  \
            *(uint2*)base              = hp;                                   \
            *(uint2*)(base + A_LO_OFF) = lp;                                   \
        }                                                                      \
    } while (0)

#define CPA_B(kt, s)                                                           \
    do {                                                                       \
        _Pragma("unroll")                                                      \
        for (int i = 0; i < 2; i++) {                                          \
            const int idx = tid + i * 512;                                     \
            const int n = idx >> 2, ku = idx & 3;                              \
            const size_t gsrc = (size_t)n * K_DIM + (kt) * 32 + ku * 8;        \
            const uint32_t d =                                                 \
                sbase + (s) * STAGE_BYTES + B_HI_OFF + n * SROWB + ku * 16;    \
            CPASYNC16(d, bH + gsrc);                                           \
            CPASYNC16(d + (B_LO_OFF - B_HI_OFF), bL + gsrc);                   \
        }                                                                      \
    } while (0)

    // prologue: chunks 0 and 1 into stages 0 and 1
    LDG_A(0); CPA_B(0, 0); CPCOMMIT(); STS_A(0);
    LDG_A(1); CPA_B(1, 1); CPCOMMIT(); STS_A(1);

    const int a_row = (lane & 7) + ((lane >> 3) & 1) * 8;
    const int a_kb  = ((lane >> 4) & 1) * 16;
    const int b_row = (lane & 7) + ((lane >> 4) & 1) * 8;
    const int b_kb  = ((lane >> 3) & 1) * 16;

    for (int kt = 0; kt < NCHUNK; kt++) {
        const int s = kt % 3;
        const int sn = (kt + 2) % 3;
        if (kt + 2 < NCHUNK) LDG_A(kt + 2);   // hide LDG latency over wait+sync
        CPWAIT1();           // chunk kt's B complete (only kt+1's group pending)
        __syncthreads();     // all warps done consuming stage sn (iter kt-1)
        if (kt + 2 < NCHUNK) {
            STS_A(sn);
            CPA_B(kt + 2, sn);
            CPCOMMIT();
        }

        const uint32_t stg = sbase + s * STAGE_BYTES;
#pragma unroll
        for (int kk = 0; kk < 2; kk++) {
            uint32_t ah[2][4], al[2][4];
#pragma unroll
            for (int mi = 0; mi < 2; mi++) {
                const uint32_t aaddr =
                    stg + (wm * 32 + mi * 16 + a_row) * SROWB + kk * 32 + a_kb;
                ldsm_x4(ah[mi][0], ah[mi][1], ah[mi][2], ah[mi][3], aaddr);
                ldsm_x4(al[mi][0], al[mi][1], al[mi][2], al[mi][3],
                        aaddr + A_LO_OFF);
            }
#pragma unroll
            for (int np = 0; np < 4; np++) {
                const uint32_t baddr = stg + B_HI_OFF +
                    (wn * 64 + np * 16 + b_row) * SROWB + kk * 32 + b_kb;
                uint32_t bh0, bh1, bh2, bh3, bl0, bl1, bl2, bl3;
                ldsm_x4(bh0, bh1, bh2, bh3, baddr);
                ldsm_x4(bl0, bl1, bl2, bl3, baddr + (B_LO_OFF - B_HI_OFF));
#pragma unroll
                for (int mi = 0; mi < 2; mi++) {
                    mma_bf16(acc[mi][np * 2],     ah[mi], bh0, bh1);
                    mma_bf16(acc[mi][np * 2 + 1], ah[mi], bh2, bh3);
                }
#pragma unroll
                for (int mi = 0; mi < 2; mi++) {
                    mma_bf16(acc[mi][np * 2],     al[mi], bh0, bh1);
                    mma_bf16(acc[mi][np * 2 + 1], al[mi], bh2, bh3);
                }
#pragma unroll
                for (int mi = 0; mi < 2; mi++) {
                    mma_bf16(acc[mi][np * 2],     ah[mi], bl0, bl1);
                    mma_bf16(acc[mi][np * 2 + 1], ah[mi], bl2, bl3);
                }
            }
        }
    }
#undef LDG_A
#undef STS_A
#undef CPA_B

    // epilogue
#pragma unroll
    for (int mi = 0; mi < 2; mi++)
#pragma unroll
        for (int ni = 0; ni < 8; ni++) {
            const int row = m0 + wm * 32 + mi * 16 + (lane >> 2);
            const int col = n0 + wn * 64 + ni * 8 + (lane & 3) * 2;
            float* p = g_xg + (size_t)row * N_DIM + col;
            float2 v0, v1;
            v0.x = acc[mi][ni][0]; v0.y = acc[mi][ni][1];
            v1.x = acc[mi][ni][2]; v1.y = acc[mi][ni][3];
            *(float2*)p = v0;
            *(float2*)(p + 8 * N_DIM) = v1;
        }
}

// ===========================================================================
// Kernel L: LSTM v4 — FFMA2 (fma.rn.f32x2), k-pair lanes, v1 exchange scheme
//   Us: [512][108] (rows 0..103 per col), rows 104..127 in 12 packed regs.
// ===========================================================================
__device__ __forceinline__ float fsig(float x) { return 1.f / (1.f + __expf(-x)); }
__device__ __forceinline__ float ftanh(float x) { return 1.f - 2.f / (__expf(2.f * x) + 1.f); }

#define USTRIDE 108
#define US_FLOATS (512 * USTRIDE)
#define SM2_FLOATS (US_FLOATS + 256 + 1024)   // + hsA/hsB + zs

__global__ __launch_bounds__(512) void lstm_rec(const float* __restrict__ Uh,
                                                const float* __restrict__ bias,
                                                const float* __restrict__ Wout,
                                                const float* __restrict__ bout,
                                                float* __restrict__ out) {
    extern __shared__ float smf[];
    float* Us  = smf;                 // [512][108]
    float* hsA = smf + US_FLOATS;     // [128] batch 0
    float* hsB = hsA + 128;           // [128] batch 1
    float* zs  = hsB + 128;           // [2][512]

    const int tid = threadIdx.x;
    const int g   = tid;
    const int b0  = blockIdx.x * 2;

    for (int k = 0; k < 104; k++) Us[g * USTRIDE + k] = Uh[k * 512 + g];
    // rows 104..127 packed as 12 f32x2 registers
    unsigned long long wpk[12];
#pragma unroll
    for (int r = 0; r < 12; r++) {
        const float e = Uh[(104 + 2 * r) * 512 + g];
        const float o = Uh[(104 + 2 * r + 1) * 512 + g];
        asm("mov.b64 %0,{%1,%2};" : "=l"(wpk[r]) : "f"(e), "f"(o));
    }
    const float bg   = bias[g];
    const int  gate  = g >> 7;

    if (tid < 256) { (tid < 128 ? hsA : hsB)[tid & 127] = 0.f; }
    float c = 0.f;
    __syncthreads();

    const float* xp0 = g_xg + ((size_t)b0 * 128) * 512 + g;
    const float* xp1 = g_xg + ((size_t)(b0 + 1) * 128) * 512 + g;
    float x0 = xp0[0];
    float x1 = xp1[0];

    const ulonglong2* uv  = (const ulonglong2*)(Us + g * USTRIDE);
    const ulonglong2* hA2 = (const ulonglong2*)hsA;
    const ulonglong2* hB2 = (const ulonglong2*)hsB;

    for (int t = 0; t < 128; t++) {
        unsigned long long d0 = 0ull, d1 = 0ull;   // (even-k, odd-k) lanes
        if (true) {
            // SMEM part: k = 0..103 (26 x 16B)
#pragma unroll
            for (int q = 0; q < 26; q++) {
                const ulonglong2 u = uv[q];
                const ulonglong2 a = hA2[q];
                const ulonglong2 b = hB2[q];
                ffma2(d0, u.x, a.x); ffma2(d0, u.y, a.y);
                ffma2(d1, u.x, b.x); ffma2(d1, u.y, b.y);
            }
            // register part: k = 104..127 (6 x 16B of h)
#pragma unroll
            for (int q = 0; q < 6; q++) {
                const ulonglong2 a = hA2[26 + q];
                const ulonglong2 b = hB2[26 + q];
                ffma2(d0, wpk[2 * q], a.x); ffma2(d0, wpk[2 * q + 1], a.y);
                ffma2(d1, wpk[2 * q], b.x); ffma2(d1, wpk[2 * q + 1], b.y);
            }
        }
        float z0 = x0 + bg + f2_sum(d0);
        float z1 = x1 + bg + f2_sum(d1);
        if (t + 1 < 128) {
            x0 = xp0[(t + 1) * 512];
            x1 = xp1[(t + 1) * 512];
        }

        float a0, a1;
        if (gate == 2) { a0 = ftanh(z0); a1 = ftanh(z1); }
        else           { a0 = fsig(z0);  a1 = fsig(z1);  }
        zs[g]       = a0;
        zs[512 + g] = a1;
        __syncthreads();

        if (tid < 256) {
            const int bl = tid >> 7;
            const int jj = tid & 127;
            const float* zb = zs + bl * 512;
            const float ig = zb[jj];
            const float fg = zb[128 + jj];
            const float gg = zb[256 + jj];
            const float og = zb[384 + jj];
            c = fg * c + ig * gg;
            (bl ? hsB : hsA)[jj] = og * ftanh(c);
        }
        __syncthreads();
    }

    // output head
    if (tid < 256) {
        const int bl = tid >> 7;
        const int jj = tid & 127;
        const float h = (bl ? hsB : hsA)[jj];
        float p0 = h * Wout[jj * 2 + 0];
        float p1 = h * Wout[jj * 2 + 1];
#pragma unroll
        for (int off = 16; off > 0; off >>= 1) {
            p0 += __shfl_down_sync(0xffffffffu, p0, off);
            p1 += __shfl_down_sync(0xffffffffu, p1, off);
        }
        if ((tid & 31) == 0) {
            const int ww = tid >> 5;
            zs[ww * 2 + 0] = p0;
            zs[ww * 2 + 1] = p1;
        }
    }
    __syncthreads();
    if (tid < 2) {
        float s0 = bout[0], s1 = bout[1];
#pragma unroll
        for (int q = 0; q < 4; q++) {
            s0 += zs[(tid * 4 + q) * 2 + 0];
            s1 += zs[(tid * 4 + q) * 2 + 1];
        }
        out[(b0 + tid) * 2 + 0] = s0;
        out[(b0 + tid) * 2 + 1] = s1;
    }
}

// ===========================================================================
extern "C" void kernel_launch(void* const* d_in, const int* in_sizes, int n_in,
                              void* d_out, int out_size) {
    const float* x    = (const float*)d_in[0];
    const float* Wi   = (const float*)d_in[1];
    const float* Uh   = (const float*)d_in[2];
    const float* b    = (const float*)d_in[3];
    const float* Wout = (const float*)d_in[4];
    const float* bout = (const float*)d_in[5];
    float* out = (float*)d_out;

    dim3 gp(K_DIM / 32, N_DIM / 32);
    prep_w<<<gp, dim3(32, 32)>>>(Wi);

    cudaFuncSetAttribute(gemm_hmma, cudaFuncAttributeMaxDynamicSharedMemorySize,
                         GEMM_SMEM);
    dim3 gg(N_DIM / 256, M_DIM / 128);          // (2, 256)
    gemm_hmma<<<gg, 512, GEMM_SMEM>>>(x);

    const size_t smem2 = SM2_FLOATS * sizeof(float);
    cudaFuncSetAttribute(lstm_rec, cudaFuncAttributeMaxDynamicSharedMemorySize,
                         (int)smem2);
    lstm_rec<<<128, 512, smem2>>>(Uh, b, Wout, bout, out);
}

// round 8
// speedup vs baseline: 1.1689x; 1.1689x over previous
#include <cuda_runtime.h>
#include <cuda_bf16.h>
#include <cstdint>
#include <cstddef>

// ---------------------------------------------------------------------------
// LSTM_87351044866551  (Round 8 = R6 baseline + ONE change: GEMM K-chunk 64)
//   P: transpose+split Wi -> g_wb_hi/lo bf16 [N=512][K=2048]
//   G: xg = x@Wi, HMMA 3-term bf16 split; 512 thr, warp 32x64, K-chunk 64,
//      2-stage ring, A-load split in halves to cap register pressure
//   L: LSTM recurrence v3 (exact R6 version)
// ---------------------------------------------------------------------------

#define M_DIM 32768
#define N_DIM 512
#define K_DIM 2048

__device__ float g_xg[(size_t)M_DIM * N_DIM];            // 64 MB scratch
__device__ __align__(256) __nv_bfloat16 g_wb_hi[(size_t)N_DIM * K_DIM];
__device__ __align__(256) __nv_bfloat16 g_wb_lo[(size_t)N_DIM * K_DIM];

// ===========================================================================
// helpers (base ISA only — tcgen05 not assemblable on this harness)
// ===========================================================================
__device__ __forceinline__ uint32_t smem_u32(const void* p) {
    uint32_t a;
    asm("{ .reg .u64 t; cvta.to.shared.u64 t, %1; cvt.u32.u64 %0, t; }"
        : "=r"(a) : "l"(p));
    return a;
}
__device__ __forceinline__ void ldsm_x4(uint32_t& r0, uint32_t& r1,
                                        uint32_t& r2, uint32_t& r3,
                                        uint32_t addr) {
    asm volatile("ldmatrix.sync.aligned.m8n8.x4.shared.b16 {%0,%1,%2,%3},[%4];"
                 : "=r"(r0), "=r"(r1), "=r"(r2), "=r"(r3) : "r"(addr));
}
__device__ __forceinline__ void mma_bf16(float* d, const uint32_t* a,
                                         uint32_t b0, uint32_t b1) {
    asm volatile(
        "mma.sync.aligned.m16n8k16.row.col.f32.bf16.bf16.f32 "
        "{%0,%1,%2,%3},{%4,%5,%6,%7},{%8,%9},{%0,%1,%2,%3};"
        : "+f"(d[0]), "+f"(d[1]), "+f"(d[2]), "+f"(d[3])
        : "r"(a[0]), "r"(a[1]), "r"(a[2]), "r"(a[3]), "r"(b0), "r"(b1));
}
#define CPASYNC16(dst, src) \
    asm volatile("cp.async.cg.shared.global [%0],[%1],16;" :: "r"(dst), "l"(src))
#define CPCOMMIT() asm volatile("cp.async.commit_group;" ::: "memory")
#define CPWAIT0()  asm volatile("cp.async.wait_group 0;" ::: "memory")

// ===========================================================================
// Kernel P: Wb_hi/lo[n][k] = split(Wi[k][n])
// ===========================================================================
__global__ __launch_bounds__(1024) void prep_w(const float* __restrict__ Wi) {
    __shared__ float t[32][33];
    const int k = blockIdx.x * 32 + threadIdx.y;
    const int n = blockIdx.y * 32 + threadIdx.x;
    t[threadIdx.y][threadIdx.x] = Wi[(size_t)k * N_DIM + n];
    __syncthreads();
    const int n2 = blockIdx.y * 32 + threadIdx.y;
    const int k2 = blockIdx.x * 32 + threadIdx.x;
    const float v = t[threadIdx.x][threadIdx.y];
    const __nv_bfloat16 h = __float2bfloat16_rn(v);
    const __nv_bfloat16 l = __float2bfloat16_rn(v - __bfloat162float(h));
    g_wb_hi[(size_t)n2 * K_DIM + k2] = h;
    g_wb_lo[(size_t)n2 * K_DIM + k2] = l;
}

// ===========================================================================
// Kernel G: HMMA GEMM, CTA 128x256, 512 thr, warp 32x64, K-chunk 64, 2-stage
// Stage (bytes, row stride 144 = 128 data + 16 pad):
//   Ahi@0 (128x144), Alo@18432, Bhi@36864 (256x144), Blo@73728 -> 110592
// ===========================================================================
#define SROWB 144
#define A_LO_OFF 18432
#define B_HI_OFF 36864
#define B_LO_OFF 73728
#define STAGE_BYTES 110592
#define GEMM_SMEM (2 * STAGE_BYTES)   // 221184
#define NCHUNK 32                     // K / 64

__global__ __launch_bounds__(512, 1) void gemm_hmma(const float* __restrict__ x) {
    extern __shared__ __nv_bfloat16 smb[];
    const uint32_t sbase = smem_u32(smb);
    const int tid  = threadIdx.x;
    const int lane = tid & 31;
    const int w    = tid >> 5;
    const int wm   = w & 3;          // 4 M-warps of 32 rows
    const int wn   = w >> 2;         // 4 N-warps of 64 cols
    const int m0   = blockIdx.y * 128;
    const int n0   = blockIdx.x * 256;

    float acc[2][8][4];
#pragma unroll
    for (int a = 0; a < 2; a++)
#pragma unroll
        for (int b = 0; b < 8; b++)
#pragma unroll
            for (int c = 0; c < 4; c++) acc[a][b][c] = 0.f;

    const float* xA = x + (size_t)m0 * K_DIM;
    const __nv_bfloat16* bH = g_wb_hi + (size_t)n0 * K_DIM;
    const __nv_bfloat16* bL = g_wb_lo + (size_t)n0 * K_DIM;

    float4 av[2];

    // A half-load: 1024 float4 (rows 64*h .. 64*h+63), 2 per thread
    // idx = tid + i*512 + h*1024; r = idx>>4 (16 float4/row), f4 = idx&15
#define LDG_AH(kt, h)                                                          \
    do {                                                                       \
        _Pragma("unroll")                                                      \
        for (int i = 0; i < 2; i++) {                                          \
            const int idx = tid + i * 512 + (h) * 1024;                        \
            const int r = idx >> 4, f4 = idx & 15;                             \
            av[i] = *(const float4*)(xA + (size_t)r * K_DIM + (kt) * 64 + f4 * 4); \
        }                                                                      \
    } while (0)

#define STS_AH(s, h)                                                           \
    do {                                                                       \
        _Pragma("unroll")                                                      \
        for (int i = 0; i < 2; i++) {                                          \
            const int idx = tid + i * 512 + (h) * 1024;                        \
            const int r = idx >> 4, f4 = idx & 15;                             \
            const float4 v = av[i];                                            \
            __nv_bfloat16 hx = __float2bfloat16_rn(v.x);                       \
            __nv_bfloat16 hy = __float2bfloat16_rn(v.y);                       \
            __nv_bfloat16 hz = __float2bfloat16_rn(v.z);                       \
            __nv_bfloat16 hw = __float2bfloat16_rn(v.w);                       \
            __nv_bfloat16 lx = __float2bfloat16_rn(v.x - __bfloat162float(hx)); \
            __nv_bfloat16 ly = __float2bfloat16_rn(v.y - __bfloat162float(hy)); \
            __nv_bfloat16 lz = __float2bfloat16_rn(v.z - __bfloat162float(hz)); \
            __nv_bfloat16 lw = __float2bfloat16_rn(v.w - __bfloat162float(hw)); \
            __nv_bfloat162 h01, h23, l01, l23;                                 \
            h01.x = hx; h01.y = hy; h23.x = hz; h23.y = hw;                    \
            l01.x = lx; l01.y = ly; l23.x = lz; l23.y = lw;                    \
            uint2 hp, lp;                                                      \
            hp.x = *(uint32_t*)&h01; hp.y = *(uint32_t*)&h23;                  \
            lp.x = *(uint32_t*)&l01; lp.y = *(uint32_t*)&l23;                  \
            char* base = (char*)smb + (s) * STAGE_BYTES + r * SROWB + f4 * 8;  \
            *(uint2*)base              = hp;                                   \
            *(uint2*)(base + A_LO_OFF) = lp;                                   \
        }                                                                      \
    } while (0)

    // B: 2048 16B units per array per chunk -> 4 idx/thread, hi+lo each
#define CPA_B(kt, s)                                                           \
    do {                                                                       \
        _Pragma("unroll")                                                      \
        for (int i = 0; i < 4; i++) {                                          \
            const int idx = tid + i * 512;                                     \
            const int n = idx >> 3, ku = idx & 7;                              \
            const size_t gsrc = (size_t)n * K_DIM + (kt) * 64 + ku * 8;        \
            const uint32_t d =                                                 \
                sbase + (s) * STAGE_BYTES + B_HI_OFF + n * SROWB + ku * 16;    \
            CPASYNC16(d, bH + gsrc);                                           \
            CPASYNC16(d + (B_LO_OFF - B_HI_OFF), bL + gsrc);                   \
        }                                                                      \
    } while (0)

    // prologue: chunk 0 into stage 0
    CPA_B(0, 0);
    CPCOMMIT();
    LDG_AH(0, 0); STS_AH(0, 0);
    LDG_AH(0, 1); STS_AH(0, 1);
    CPWAIT0();
    __syncthreads();

    const int a_row = (lane & 7) + ((lane >> 3) & 1) * 8;
    const int a_kb  = ((lane >> 4) & 1) * 16;
    const int b_row = (lane & 7) + ((lane >> 4) & 1) * 8;
    const int b_kb  = ((lane >> 3) & 1) * 16;

    for (int kt = 0; kt < NCHUNK; kt++) {
        const int s = kt & 1;
        const bool more = (kt + 1 < NCHUNK);
        if (more) {
            CPA_B(kt + 1, s ^ 1);   // ~full MMA chunk of latency budget
            CPCOMMIT();
            LDG_AH(kt + 1, 0);
        }

        const uint32_t stg = sbase + s * STAGE_BYTES;
        // ---- first half: kk = 0,1 ----
#pragma unroll
        for (int kk = 0; kk < 2; kk++) {
            uint32_t ah[2][4], al[2][4];
#pragma unroll
            for (int mi = 0; mi < 2; mi++) {
                const uint32_t aaddr =
                    stg + (wm * 32 + mi * 16 + a_row) * SROWB + kk * 32 + a_kb;
                ldsm_x4(ah[mi][0], ah[mi][1], ah[mi][2], ah[mi][3], aaddr);
                ldsm_x4(al[mi][0], al[mi][1], al[mi][2], al[mi][3],
                        aaddr + A_LO_OFF);
            }
#pragma unroll
            for (int np = 0; np < 4; np++) {
                const uint32_t baddr = stg + B_HI_OFF +
                    (wn * 64 + np * 16 + b_row) * SROWB + kk * 32 + b_kb;
                uint32_t bh0, bh1, bh2, bh3, bl0, bl1, bl2, bl3;
                ldsm_x4(bh0, bh1, bh2, bh3, baddr);
                ldsm_x4(bl0, bl1, bl2, bl3, baddr + (B_LO_OFF - B_HI_OFF));
#pragma unroll
                for (int mi = 0; mi < 2; mi++) {
                    mma_bf16(acc[mi][np * 2],     ah[mi], bh0, bh1);
                    mma_bf16(acc[mi][np * 2 + 1], ah[mi], bh2, bh3);
                }
#pragma unroll
                for (int mi = 0; mi < 2; mi++) {
                    mma_bf16(acc[mi][np * 2],     al[mi], bh0, bh1);
                    mma_bf16(acc[mi][np * 2 + 1], al[mi], bh2, bh3);
                }
#pragma unroll
                for (int mi = 0; mi < 2; mi++) {
                    mma_bf16(acc[mi][np * 2],     ah[mi], bl0, bl1);
                    mma_bf16(acc[mi][np * 2 + 1], ah[mi], bl2, bl3);
                }
            }
        }
        if (more) {
            STS_AH(s ^ 1, 0);       // frees av, then refill with half 1
            LDG_AH(kt + 1, 1);
        }
        // ---- second half: kk = 2,3 ----
#pragma unroll
        for (int kk = 2; kk < 4; kk++) {
            uint32_t ah[2][4], al[2][4];
#pragma unroll
            for (int mi = 0; mi < 2; mi++) {
                const uint32_t aaddr =
                    stg + (wm * 32 + mi * 16 + a_row) * SROWB + kk * 32 + a_kb;
                ldsm_x4(ah[mi][0], ah[mi][1], ah[mi][2], ah[mi][3], aaddr);
                ldsm_x4(al[mi][0], al[mi][1], al[mi][2], al[mi][3],
                        aaddr + A_LO_OFF);
            }
#pragma unroll
            for (int np = 0; np < 4; np++) {
                const uint32_t baddr = stg + B_HI_OFF +
                    (wn * 64 + np * 16 + b_row) * SROWB + kk * 32 + b_kb;
                uint32_t bh0, bh1, bh2, bh3, bl0, bl1, bl2, bl3;
                ldsm_x4(bh0, bh1, bh2, bh3, baddr);
                ldsm_x4(bl0, bl1, bl2, bl3, baddr + (B_LO_OFF - B_HI_OFF));
#pragma unroll
                for (int mi = 0; mi < 2; mi++) {
                    mma_bf16(acc[mi][np * 2],     ah[mi], bh0, bh1);
                    mma_bf16(acc[mi][np * 2 + 1], ah[mi], bh2, bh3);
                }
#pragma unroll
                for (int mi = 0; mi < 2; mi++) {
                    mma_bf16(acc[mi][np * 2],     al[mi], bh0, bh1);
                    mma_bf16(acc[mi][np * 2 + 1], al[mi], bh2, bh3);
                }
#pragma unroll
                for (int mi = 0; mi < 2; mi++) {
                    mma_bf16(acc[mi][np * 2],     ah[mi], bl0, bl1);
                    mma_bf16(acc[mi][np * 2 + 1], ah[mi], bl2, bl3);
                }
            }
        }
        if (more) {
            STS_AH(s ^ 1, 1);
            CPWAIT0();
        }
        __syncthreads();
    }
#undef LDG_AH
#undef STS_AH
#undef CPA_B

    // epilogue
#pragma unroll
    for (int mi = 0; mi < 2; mi++)
#pragma unroll
        for (int ni = 0; ni < 8; ni++) {
            const int row = m0 + wm * 32 + mi * 16 + (lane >> 2);
            const int col = n0 + wn * 64 + ni * 8 + (lane & 3) * 2;
            float* p = g_xg + (size_t)row * N_DIM + col;
            float2 v0, v1;
            v0.x = acc[mi][ni][0]; v0.y = acc[mi][ni][1];
            v1.x = acc[mi][ni][2]; v1.y = acc[mi][ni][3];
            *(float2*)p = v0;
            *(float2*)(p + 8 * N_DIM) = v1;
        }
}

// ===========================================================================
// Kernel L: LSTM recurrence v3 (exact R6 version)
// ===========================================================================
__device__ __forceinline__ float fsig(float x) { return 1.f / (1.f + __expf(-x)); }
__device__ __forceinline__ float ftanh(float x) { return 1.f - 2.f / (__expf(2.f * x) + 1.f); }

#define USTRIDE 68
#define US_FLOATS (512 * USTRIDE)
#define SM2_FLOATS (US_FLOATS + 256 + 1024)

__global__ __launch_bounds__(512) void lstm_rec(const float* __restrict__ Uh,
                                                const float* __restrict__ bias,
                                                const float* __restrict__ Wout,
                                                const float* __restrict__ bout,
                                                float* __restrict__ out) {
    extern __shared__ float smf[];
    float* Us = smf;                 // [512][68], rows 0..63 of Uh per column
    float* hs = smf + US_FLOATS;     // [2][128]
    float* zs = hs + 256;            // [2][512]

    const int tid = threadIdx.x;
    const int g   = tid;
    const int b0  = blockIdx.x * 2;

    for (int k = 0; k < 64; k++) Us[g * USTRIDE + k] = Uh[k * 512 + g];
    float wreg[64];
#pragma unroll
    for (int r = 0; r < 64; r++) wreg[r] = Uh[(64 + r) * 512 + g];
    const float bg   = bias[g];
    const int  gate  = g >> 7;

    if (tid < 256) hs[tid] = 0.f;
    float c = 0.f;
    __syncthreads();

    const float* xp0 = g_xg + ((size_t)b0 * 128) * 512 + g;
    const float* xp1 = g_xg + ((size_t)(b0 + 1) * 128) * 512 + g;
    float x0 = xp0[0];
    float x1 = xp1[0];

    for (int t = 0; t < 128; t++) {
        float z0 = x0 + bg;
        float z1 = x1 + bg;
        if (t + 1 < 128) {
            x0 = xp0[(t + 1) * 512];
            x1 = xp1[(t + 1) * 512];
        }

        const float4* uv = (const float4*)(Us + g * USTRIDE);
        const float4* h0 = (const float4*)hs;
        const float4* h1 = (const float4*)(hs + 128);
#pragma unroll
        for (int q = 0; q < 16; q++) {
            const float4 u  = uv[q];
            const float4 ha = h0[q];
            const float4 hb = h1[q];
            z0 += u.x * ha.x; z0 += u.y * ha.y; z0 += u.z * ha.z; z0 += u.w * ha.w;
            z1 += u.x * hb.x; z1 += u.y * hb.y; z1 += u.z * hb.z; z1 += u.w * hb.w;
        }
#pragma unroll
        for (int q = 0; q < 16; q++) {
            const float4 ha = h0[16 + q];
            const float4 hb = h1[16 + q];
            z0 += wreg[q * 4 + 0] * ha.x; z0 += wreg[q * 4 + 1] * ha.y;
            z0 += wreg[q * 4 + 2] * ha.z; z0 += wreg[q * 4 + 3] * ha.w;
            z1 += wreg[q * 4 + 0] * hb.x; z1 += wreg[q * 4 + 1] * hb.y;
            z1 += wreg[q * 4 + 2] * hb.z; z1 += wreg[q * 4 + 3] * hb.w;
        }

        float a0, a1;
        if (gate == 2) { a0 = ftanh(z0); a1 = ftanh(z1); }
        else           { a0 = fsig(z0);  a1 = fsig(z1);  }
        zs[g]       = a0;
        zs[512 + g] = a1;
        __syncthreads();

        if (tid < 256) {
            const int bl = tid >> 7;
            const int jj = tid & 127;
            const float* zb = zs + bl * 512;
            const float ig = zb[jj];
            const float fg = zb[128 + jj];
            const float gg = zb[256 + jj];
            const float og = zb[384 + jj];
            c = fg * c + ig * gg;
            hs[bl * 128 + jj] = og * ftanh(c);
        }
        __syncthreads();
    }

    if (tid < 256) {
        const int bl = tid >> 7;
        const int jj = tid & 127;
        const float h = hs[bl * 128 + jj];
        float p0 = h * Wout[jj * 2 + 0];
        float p1 = h * Wout[jj * 2 + 1];
#pragma unroll
        for (int off = 16; off > 0; off >>= 1) {
            p0 += __shfl_down_sync(0xffffffffu, p0, off);
            p1 += __shfl_down_sync(0xffffffffu, p1, off);
        }
        if ((tid & 31) == 0) {
            const int w = tid >> 5;
            zs[w * 2 + 0] = p0;
            zs[w * 2 + 1] = p1;
        }
    }
    __syncthreads();
    if (tid < 2) {
        float s0 = bout[0], s1 = bout[1];
#pragma unroll
        for (int w = 0; w < 4; w++) {
            s0 += zs[(tid * 4 + w) * 2 + 0];
            s1 += zs[(tid * 4 + w) * 2 + 1];
        }
        out[(b0 + tid) * 2 + 0] = s0;
        out[(b0 + tid) * 2 + 1] = s1;
    }
}

// ===========================================================================
extern "C" void kernel_launch(void* const* d_in, const int* in_sizes, int n_in,
                              void* d_out, int out_size) {
    const float* x    = (const float*)d_in[0];
    const float* Wi   = (const float*)d_in[1];
    const float* Uh   = (const float*)d_in[2];
    const float* b    = (const float*)d_in[3];
    const float* Wout = (const float*)d_in[4];
    const float* bout = (const float*)d_in[5];
    float* out = (float*)d_out;

    dim3 gp(K_DIM / 32, N_DIM / 32);
    prep_w<<<gp, dim3(32, 32)>>>(Wi);

    cudaFuncSetAttribute(gemm_hmma, cudaFuncAttributeMaxDynamicSharedMemorySize,
                         GEMM_SMEM);
    dim3 gg(N_DIM / 256, M_DIM / 128);          // (2, 256)
    gemm_hmma<<<gg, 512, GEMM_SMEM>>>(x);

    const size_t smem2 = SM2_FLOATS * sizeof(float);
    cudaFuncSetAttribute(lstm_rec, cudaFuncAttributeMaxDynamicSharedMemorySize,
                         (int)smem2);
    lstm_rec<<<128, 512, smem2>>>(Uh, b, Wout, bout, out);
}

// round 9
// speedup vs baseline: 1.4915x; 1.2760x over previous
#include <cuda_runtime.h>
#include <cuda_fp16.h>
#include <cstdint>
#include <cstddef>

// ---------------------------------------------------------------------------
// LSTM_87351044866551  (Round 9 = R8 + ONE change: GEMM 2-term fp16 split)
//   P: transpose+split Wi -> g_wh/g_wl fp16 [N=512][K=2048]
//   G: xg = x16 @ (W_hi + W_lo), HMMA fp16; 512 thr, warp 32x64, K-chunk 64
//   L: LSTM recurrence v3 (exact R6/R8 version)
// ---------------------------------------------------------------------------

#define M_DIM 32768
#define N_DIM 512
#define K_DIM 2048

__device__ float g_xg[(size_t)M_DIM * N_DIM];            // 64 MB scratch
__device__ __align__(256) __half g_wh[(size_t)N_DIM * K_DIM];
__device__ __align__(256) __half g_wl[(size_t)N_DIM * K_DIM];

// ===========================================================================
// helpers (base ISA only — tcgen05 not assemblable on this harness)
// ===========================================================================
__device__ __forceinline__ uint32_t smem_u32(const void* p) {
    uint32_t a;
    asm("{ .reg .u64 t; cvta.to.shared.u64 t, %1; cvt.u32.u64 %0, t; }"
        : "=r"(a) : "l"(p));
    return a;
}
__device__ __forceinline__ void ldsm_x4(uint32_t& r0, uint32_t& r1,
                                        uint32_t& r2, uint32_t& r3,
                                        uint32_t addr) {
    asm volatile("ldmatrix.sync.aligned.m8n8.x4.shared.b16 {%0,%1,%2,%3},[%4];"
                 : "=r"(r0), "=r"(r1), "=r"(r2), "=r"(r3) : "r"(addr));
}
__device__ __forceinline__ void mma_f16(float* d, const uint32_t* a,
                                        uint32_t b0, uint32_t b1) {
    asm volatile(
        "mma.sync.aligned.m16n8k16.row.col.f32.f16.f16.f32 "
        "{%0,%1,%2,%3},{%4,%5,%6,%7},{%8,%9},{%0,%1,%2,%3};"
        : "+f"(d[0]), "+f"(d[1]), "+f"(d[2]), "+f"(d[3])
        : "r"(a[0]), "r"(a[1]), "r"(a[2]), "r"(a[3]), "r"(b0), "r"(b1));
}
#define CPASYNC16(dst, src) \
    asm volatile("cp.async.cg.shared.global [%0],[%1],16;" :: "r"(dst), "l"(src))
#define CPCOMMIT() asm volatile("cp.async.commit_group;" ::: "memory")
#define CPWAIT0()  asm volatile("cp.async.wait_group 0;" ::: "memory")

// ===========================================================================
// Kernel P: Wh/Wl[n][k] = fp16 split of Wi[k][n]
// ===========================================================================
__global__ __launch_bounds__(1024) void prep_w(const float* __restrict__ Wi) {
    __shared__ float t[32][33];
    const int k = blockIdx.x * 32 + threadIdx.y;
    const int n = blockIdx.y * 32 + threadIdx.x;
    t[threadIdx.y][threadIdx.x] = Wi[(size_t)k * N_DIM + n];
    __syncthreads();
    const int n2 = blockIdx.y * 32 + threadIdx.y;
    const int k2 = blockIdx.x * 32 + threadIdx.x;
    const float v = t[threadIdx.x][threadIdx.y];
    const __half h = __float2half_rn(v);
    const __half l = __float2half_rn(v - __half2float(h));
    g_wh[(size_t)n2 * K_DIM + k2] = h;
    g_wl[(size_t)n2 * K_DIM + k2] = l;
}

// ===========================================================================
// Kernel G: HMMA fp16 GEMM, CTA 128x256, 512 thr, warp 32x64, K-chunk 64
// Stage (bytes, row stride 144 = 128 data + 16 pad):
//   A@0 (128x144), Bhi@18432 (256x144), Blo@55296 -> 92160; 2 stages = 184320
// ===========================================================================
#define SROWB 144
#define B_HI_OFF 18432
#define B_LO_OFF 55296
#define STAGE_BYTES 92160
#define GEMM_SMEM (2 * STAGE_BYTES)   // 184320
#define NCHUNK 32                     // K / 64

__global__ __launch_bounds__(512, 1) void gemm_hmma(const float* __restrict__ x) {
    extern __shared__ __half smb[];
    const uint32_t sbase = smem_u32(smb);
    const int tid  = threadIdx.x;
    const int lane = tid & 31;
    const int w    = tid >> 5;
    const int wm   = w & 3;          // 4 M-warps of 32 rows
    const int wn   = w >> 2;         // 4 N-warps of 64 cols
    const int m0   = blockIdx.y * 128;
    const int n0   = blockIdx.x * 256;

    float acc[2][8][4];
#pragma unroll
    for (int a = 0; a < 2; a++)
#pragma unroll
        for (int b = 0; b < 8; b++)
#pragma unroll
            for (int c = 0; c < 4; c++) acc[a][b][c] = 0.f;

    const float* xA = x + (size_t)m0 * K_DIM;
    const __half* bH = g_wh + (size_t)n0 * K_DIM;
    const __half* bL = g_wl + (size_t)n0 * K_DIM;

    float4 av[2];

    // A half-load: 1024 float4 (rows 64*h .. 64*h+63), 2 per thread
#define LDG_AH(kt, h)                                                          \
    do {                                                                       \
        _Pragma("unroll")                                                      \
        for (int i = 0; i < 2; i++) {                                          \
            const int idx = tid + i * 512 + (h) * 1024;                        \
            const int r = idx >> 4, f4 = idx & 15;                             \
            av[i] = *(const float4*)(xA + (size_t)r * K_DIM + (kt) * 64 + f4 * 4); \
        }                                                                      \
    } while (0)

#define STS_AH(s, h)                                                           \
    do {                                                                       \
        _Pragma("unroll")                                                      \
        for (int i = 0; i < 2; i++) {                                          \
            const int idx = tid + i * 512 + (h) * 1024;                        \
            const int r = idx >> 4, f4 = idx & 15;                             \
            const float4 v = av[i];                                            \
            __half2 p01, p23;                                                  \
            p01.x = __float2half_rn(v.x); p01.y = __float2half_rn(v.y);        \
            p23.x = __float2half_rn(v.z); p23.y = __float2half_rn(v.w);        \
            uint2 hp;                                                          \
            hp.x = *(uint32_t*)&p01; hp.y = *(uint32_t*)&p23;                  \
            *(uint2*)((char*)smb + (s) * STAGE_BYTES + r * SROWB + f4 * 8) = hp; \
        }                                                                      \
    } while (0)

    // B: 2048 16B units per array per chunk -> 4 idx/thread, hi+lo each
#define CPA_B(kt, s)                                                           \
    do {                                                                       \
        _Pragma("unroll")                                                      \
        for (int i = 0; i < 4; i++) {                                          \
            const int idx = tid + i * 512;                                     \
            const int n = idx >> 3, ku = idx & 7;                              \
            const size_t gsrc = (size_t)n * K_DIM + (kt) * 64 + ku * 8;        \
            const uint32_t d =                                                 \
                sbase + (s) * STAGE_BYTES + B_HI_OFF + n * SROWB + ku * 16;    \
            CPASYNC16(d, bH + gsrc);                                           \
            CPASYNC16(d + (B_LO_OFF - B_HI_OFF), bL + gsrc);                   \
        }                                                                      \
    } while (0)

    // prologue: chunk 0 into stage 0
    CPA_B(0, 0);
    CPCOMMIT();
    LDG_AH(0, 0); STS_AH(0, 0);
    LDG_AH(0, 1); STS_AH(0, 1);
    CPWAIT0();
    __syncthreads();

    const int a_row = (lane & 7) + ((lane >> 3) & 1) * 8;
    const int a_kb  = ((lane >> 4) & 1) * 16;
    const int b_row = (lane & 7) + ((lane >> 4) & 1) * 8;
    const int b_kb  = ((lane >> 3) & 1) * 16;

    for (int kt = 0; kt < NCHUNK; kt++) {
        const int s = kt & 1;
        const bool more = (kt + 1 < NCHUNK);
        if (more) {
            CPA_B(kt + 1, s ^ 1);
            CPCOMMIT();
            LDG_AH(kt + 1, 0);
        }

        const uint32_t stg = sbase + s * STAGE_BYTES;
        // ---- first half: kk = 0,1 ----
#pragma unroll
        for (int kk = 0; kk < 2; kk++) {
            uint32_t ah[2][4];
#pragma unroll
            for (int mi = 0; mi < 2; mi++) {
                const uint32_t aaddr =
                    stg + (wm * 32 + mi * 16 + a_row) * SROWB + kk * 32 + a_kb;
                ldsm_x4(ah[mi][0], ah[mi][1], ah[mi][2], ah[mi][3], aaddr);
            }
#pragma unroll
            for (int np = 0; np < 4; np++) {
                const uint32_t baddr = stg + B_HI_OFF +
                    (wn * 64 + np * 16 + b_row) * SROWB + kk * 32 + b_kb;
                uint32_t bh0, bh1, bh2, bh3, bl0, bl1, bl2, bl3;
                ldsm_x4(bh0, bh1, bh2, bh3, baddr);
                ldsm_x4(bl0, bl1, bl2, bl3, baddr + (B_LO_OFF - B_HI_OFF));
#pragma unroll
                for (int mi = 0; mi < 2; mi++) {
                    mma_f16(acc[mi][np * 2],     ah[mi], bh0, bh1);
                    mma_f16(acc[mi][np * 2 + 1], ah[mi], bh2, bh3);
                }
#pragma unroll
                for (int mi = 0; mi < 2; mi++) {
                    mma_f16(acc[mi][np * 2],     ah[mi], bl0, bl1);
                    mma_f16(acc[mi][np * 2 + 1], ah[mi], bl2, bl3);
                }
            }
        }
        if (more) {
            STS_AH(s ^ 1, 0);
            LDG_AH(kt + 1, 1);
        }
        // ---- second half: kk = 2,3 ----
#pragma unroll
        for (int kk = 2; kk < 4; kk++) {
            uint32_t ah[2][4];
#pragma unroll
            for (int mi = 0; mi < 2; mi++) {
                const uint32_t aaddr =
                    stg + (wm * 32 + mi * 16 + a_row) * SROWB + kk * 32 + a_kb;
                ldsm_x4(ah[mi][0], ah[mi][1], ah[mi][2], ah[mi][3], aaddr);
            }
#pragma unroll
            for (int np = 0; np < 4; np++) {
                const uint32_t baddr = stg + B_HI_OFF +
                    (wn * 64 + np * 16 + b_row) * SROWB + kk * 32 + b_kb;
                uint32_t bh0, bh1, bh2, bh3, bl0, bl1, bl2, bl3;
                ldsm_x4(bh0, bh1, bh2, bh3, baddr);
                ldsm_x4(bl0, bl1, bl2, bl3, baddr + (B_LO_OFF - B_HI_OFF));
#pragma unroll
                for (int mi = 0; mi < 2; mi++) {
                    mma_f16(acc[mi][np * 2],     ah[mi], bh0, bh1);
                    mma_f16(acc[mi][np * 2 + 1], ah[mi], bh2, bh3);
                }
#pragma unroll
                for (int mi = 0; mi < 2; mi++) {
                    mma_f16(acc[mi][np * 2],     ah[mi], bl0, bl1);
                    mma_f16(acc[mi][np * 2 + 1], ah[mi], bl2, bl3);
                }
            }
        }
        if (more) {
            STS_AH(s ^ 1, 1);
            CPWAIT0();
        }
        __syncthreads();
    }
#undef LDG_AH
#undef STS_AH
#undef CPA_B

    // epilogue
#pragma unroll
    for (int mi = 0; mi < 2; mi++)
#pragma unroll
        for (int ni = 0; ni < 8; ni++) {
            const int row = m0 + wm * 32 + mi * 16 + (lane >> 2);
            const int col = n0 + wn * 64 + ni * 8 + (lane & 3) * 2;
            float* p = g_xg + (size_t)row * N_DIM + col;
            float2 v0, v1;
            v0.x = acc[mi][ni][0]; v0.y = acc[mi][ni][1];
            v1.x = acc[mi][ni][2]; v1.y = acc[mi][ni][3];
            *(float2*)p = v0;
            *(float2*)(p + 8 * N_DIM) = v1;
        }
}

// ===========================================================================
// Kernel L: LSTM recurrence v3 (exact R6/R8 version)
// ===========================================================================
__device__ __forceinline__ float fsig(float x) { return 1.f / (1.f + __expf(-x)); }
__device__ __forceinline__ float ftanh(float x) { return 1.f - 2.f / (__expf(2.f * x) + 1.f); }

#define USTRIDE 68
#define US_FLOATS (512 * USTRIDE)
#define SM2_FLOATS (US_FLOATS + 256 + 1024)

__global__ __launch_bounds__(512) void lstm_rec(const float* __restrict__ Uh,
                                                const float* __restrict__ bias,
                                                const float* __restrict__ Wout,
                                                const float* __restrict__ bout,
                                                float* __restrict__ out) {
    extern __shared__ float smf[];
    float* Us = smf;                 // [512][68], rows 0..63 of Uh per column
    float* hs = smf + US_FLOATS;     // [2][128]
    float* zs = hs + 256;            // [2][512]

    const int tid = threadIdx.x;
    const int g   = tid;
    const int b0  = blockIdx.x * 2;

    for (int k = 0; k < 64; k++) Us[g * USTRIDE + k] = Uh[k * 512 + g];
    float wreg[64];
#pragma unroll
    for (int r = 0; r < 64; r++) wreg[r] = Uh[(64 + r) * 512 + g];
    const float bg   = bias[g];
    const int  gate  = g >> 7;

    if (tid < 256) hs[tid] = 0.f;
    float c = 0.f;
    __syncthreads();

    const float* xp0 = g_xg + ((size_t)b0 * 128) * 512 + g;
    const float* xp1 = g_xg + ((size_t)(b0 + 1) * 128) * 512 + g;
    float x0 = xp0[0];
    float x1 = xp1[0];

    for (int t = 0; t < 128; t++) {
        float z0 = x0 + bg;
        float z1 = x1 + bg;
        if (t + 1 < 128) {
            x0 = xp0[(t + 1) * 512];
            x1 = xp1[(t + 1) * 512];
        }

        const float4* uv = (const float4*)(Us + g * USTRIDE);
        const float4* h0 = (const float4*)hs;
        const float4* h1 = (const float4*)(hs + 128);
#pragma unroll
        for (int q = 0; q < 16; q++) {
            const float4 u  = uv[q];
            const float4 ha = h0[q];
            const float4 hb = h1[q];
            z0 += u.x * ha.x; z0 += u.y * ha.y; z0 += u.z * ha.z; z0 += u.w * ha.w;
            z1 += u.x * hb.x; z1 += u.y * hb.y; z1 += u.z * hb.z; z1 += u.w * hb.w;
        }
#pragma unroll
        for (int q = 0; q < 16; q++) {
            const float4 ha = h0[16 + q];
            const float4 hb = h1[16 + q];
            z0 += wreg[q * 4 + 0] * ha.x; z0 += wreg[q * 4 + 1] * ha.y;
            z0 += wreg[q * 4 + 2] * ha.z; z0 += wreg[q * 4 + 3] * ha.w;
            z1 += wreg[q * 4 + 0] * hb.x; z1 += wreg[q * 4 + 1] * hb.y;
            z1 += wreg[q * 4 + 2] * hb.z; z1 += wreg[q * 4 + 3] * hb.w;
        }

        float a0, a1;
        if (gate == 2) { a0 = ftanh(z0); a1 = ftanh(z1); }
        else           { a0 = fsig(z0);  a1 = fsig(z1);  }
        zs[g]       = a0;
        zs[512 + g] = a1;
        __syncthreads();

        if (tid < 256) {
            const int bl = tid >> 7;
            const int jj = tid & 127;
            const float* zb = zs + bl * 512;
            const float ig = zb[jj];
            const float fg = zb[128 + jj];
            const float gg = zb[256 + jj];
            const float og = zb[384 + jj];
            c = fg * c + ig * gg;
            hs[bl * 128 + jj] = og * ftanh(c);
        }
        __syncthreads();
    }

    if (tid < 256) {
        const int bl = tid >> 7;
        const int jj = tid & 127;
        const float h = hs[bl * 128 + jj];
        float p0 = h * Wout[jj * 2 + 0];
        float p1 = h * Wout[jj * 2 + 1];
#pragma unroll
        for (int off = 16; off > 0; off >>= 1) {
            p0 += __shfl_down_sync(0xffffffffu, p0, off);
            p1 += __shfl_down_sync(0xffffffffu, p1, off);
        }
        if ((tid & 31) == 0) {
            const int w = tid >> 5;
            zs[w * 2 + 0] = p0;
            zs[w * 2 + 1] = p1;
        }
    }
    __syncthreads();
    if (tid < 2) {
        float s0 = bout[0], s1 = bout[1];
#pragma unroll
        for (int w = 0; w < 4; w++) {
            s0 += zs[(tid * 4 + w) * 2 + 0];
            s1 += zs[(tid * 4 + w) * 2 + 1];
        }
        out[(b0 + tid) * 2 + 0] = s0;
        out[(b0 + tid) * 2 + 1] = s1;
    }
}

// ===========================================================================
extern "C" void kernel_launch(void* const* d_in, const int* in_sizes, int n_in,
                              void* d_out, int out_size) {
    const float* x    = (const float*)d_in[0];
    const float* Wi   = (const float*)d_in[1];
    const float* Uh   = (const float*)d_in[2];
    const float* b    = (const float*)d_in[3];
    const float* Wout = (const float*)d_in[4];
    const float* bout = (const float*)d_in[5];
    float* out = (float*)d_out;

    dim3 gp(K_DIM / 32, N_DIM / 32);
    prep_w<<<gp, dim3(32, 32)>>>(Wi);

    cudaFuncSetAttribute(gemm_hmma, cudaFuncAttributeMaxDynamicSharedMemorySize,
                         GEMM_SMEM);
    dim3 gg(N_DIM / 256, M_DIM / 128);          // (2, 256)
    gemm_hmma<<<gg, 512, GEMM_SMEM>>>(x);

    const size_t smem2 = SM2_FLOATS * sizeof(float);
    cudaFuncSetAttribute(lstm_rec, cudaFuncAttributeMaxDynamicSharedMemorySize,
                         (int)smem2);
    lstm_rec<<<128, 512, smem2>>>(Uh, b, Wout, bout, out);
}

// round 10
// speedup vs baseline: 1.4925x; 1.0006x over previous
#include <cuda_runtime.h>
#include <cuda_fp16.h>
#include <cstdint>
#include <cstddef>

// ---------------------------------------------------------------------------
// LSTM_87351044866551  (Round 10 = R9 + ONE change: lstm inner product FFMA2)
//   P: transpose+split Wi -> g_wh/g_wl fp16 [N=512][K=2048]
//   G: xg = x16 @ (W_hi + W_lo), HMMA fp16 (exact R9 version)
//   L: LSTM recurrence v5: v3 structure, fma.rn.f32x2 packed inner product
// ---------------------------------------------------------------------------

#define M_DIM 32768
#define N_DIM 512
#define K_DIM 2048

__device__ float g_xg[(size_t)M_DIM * N_DIM];            // 64 MB scratch
__device__ __align__(256) __half g_wh[(size_t)N_DIM * K_DIM];
__device__ __align__(256) __half g_wl[(size_t)N_DIM * K_DIM];

// ===========================================================================
// helpers (base ISA only — tcgen05 not assemblable on this harness)
// ===========================================================================
__device__ __forceinline__ uint32_t smem_u32(const void* p) {
    uint32_t a;
    asm("{ .reg .u64 t; cvta.to.shared.u64 t, %1; cvt.u32.u64 %0, t; }"
        : "=r"(a) : "l"(p));
    return a;
}
__device__ __forceinline__ void ldsm_x4(uint32_t& r0, uint32_t& r1,
                                        uint32_t& r2, uint32_t& r3,
                                        uint32_t addr) {
    asm volatile("ldmatrix.sync.aligned.m8n8.x4.shared.b16 {%0,%1,%2,%3},[%4];"
                 : "=r"(r0), "=r"(r1), "=r"(r2), "=r"(r3) : "r"(addr));
}
__device__ __forceinline__ void mma_f16(float* d, const uint32_t* a,
                                        uint32_t b0, uint32_t b1) {
    asm volatile(
        "mma.sync.aligned.m16n8k16.row.col.f32.f16.f16.f32 "
        "{%0,%1,%2,%3},{%4,%5,%6,%7},{%8,%9},{%0,%1,%2,%3};"
        : "+f"(d[0]), "+f"(d[1]), "+f"(d[2]), "+f"(d[3])
        : "r"(a[0]), "r"(a[1]), "r"(a[2]), "r"(a[3]), "r"(b0), "r"(b1));
}
#define CPASYNC16(dst, src) \
    asm volatile("cp.async.cg.shared.global [%0],[%1],16;" :: "r"(dst), "l"(src))
#define CPCOMMIT() asm volatile("cp.async.commit_group;" ::: "memory")
#define CPWAIT0()  asm volatile("cp.async.wait_group 0;" ::: "memory")

// packed dual-fp32 FMA: d = a*b + d (lanewise) — FFMA2
__device__ __forceinline__ void ffma2(unsigned long long& d,
                                      unsigned long long a,
                                      unsigned long long b) {
    asm("fma.rn.f32x2 %0, %1, %2, %0;" : "+l"(d) : "l"(a), "l"(b));
}
__device__ __forceinline__ float f2_sum(unsigned long long d) {
    float lo, hi;
    asm("mov.b64 {%0,%1}, %2;" : "=f"(lo), "=f"(hi) : "l"(d));
    return lo + hi;
}

// ===========================================================================
// Kernel P: Wh/Wl[n][k] = fp16 split of Wi[k][n]
// ===========================================================================
__global__ __launch_bounds__(1024) void prep_w(const float* __restrict__ Wi) {
    __shared__ float t[32][33];
    const int k = blockIdx.x * 32 + threadIdx.y;
    const int n = blockIdx.y * 32 + threadIdx.x;
    t[threadIdx.y][threadIdx.x] = Wi[(size_t)k * N_DIM + n];
    __syncthreads();
    const int n2 = blockIdx.y * 32 + threadIdx.y;
    const int k2 = blockIdx.x * 32 + threadIdx.x;
    const float v = t[threadIdx.x][threadIdx.y];
    const __half h = __float2half_rn(v);
    const __half l = __float2half_rn(v - __half2float(h));
    g_wh[(size_t)n2 * K_DIM + k2] = h;
    g_wl[(size_t)n2 * K_DIM + k2] = l;
}

// ===========================================================================
// Kernel G: HMMA fp16 GEMM, CTA 128x256, 512 thr, warp 32x64, K-chunk 64
// (exact R9 version)
// ===========================================================================
#define SROWB 144
#define B_HI_OFF 18432
#define B_LO_OFF 55296
#define STAGE_BYTES 92160
#define GEMM_SMEM (2 * STAGE_BYTES)   // 184320
#define NCHUNK 32                     // K / 64

__global__ __launch_bounds__(512, 1) void gemm_hmma(const float* __restrict__ x) {
    extern __shared__ __half smb[];
    const uint32_t sbase = smem_u32(smb);
    const int tid  = threadIdx.x;
    const int lane = tid & 31;
    const int w    = tid >> 5;
    const int wm   = w & 3;
    const int wn   = w >> 2;
    const int m0   = blockIdx.y * 128;
    const int n0   = blockIdx.x * 256;

    float acc[2][8][4];
#pragma unroll
    for (int a = 0; a < 2; a++)
#pragma unroll
        for (int b = 0; b < 8; b++)
#pragma unroll
            for (int c = 0; c < 4; c++) acc[a][b][c] = 0.f;

    const float* xA = x + (size_t)m0 * K_DIM;
    const __half* bH = g_wh + (size_t)n0 * K_DIM;
    const __half* bL = g_wl + (size_t)n0 * K_DIM;

    float4 av[2];

#define LDG_AH(kt, h)                                                          \
    do {                                                                       \
        _Pragma("unroll")                                                      \
        for (int i = 0; i < 2; i++) {                                          \
            const int idx = tid + i * 512 + (h) * 1024;                        \
            const int r = idx >> 4, f4 = idx & 15;                             \
            av[i] = *(const float4*)(xA + (size_t)r * K_DIM + (kt) * 64 + f4 * 4); \
        }                                                                      \
    } while (0)

#define STS_AH(s, h)                                                           \
    do {                                                                       \
        _Pragma("unroll")                                                      \
        for (int i = 0; i < 2; i++) {                                          \
            const int idx = tid + i * 512 + (h) * 1024;                        \
            const int r = idx >> 4, f4 = idx & 15;                             \
            const float4 v = av[i];                                            \
            __half2 p01, p23;                                                  \
            p01.x = __float2half_rn(v.x); p01.y = __float2half_rn(v.y);        \
            p23.x = __float2half_rn(v.z); p23.y = __float2half_rn(v.w);        \
            uint2 hp;                                                          \
            hp.x = *(uint32_t*)&p01; hp.y = *(uint32_t*)&p23;                  \
            *(uint2*)((char*)smb + (s) * STAGE_BYTES + r * SROWB + f4 * 8) = hp; \
        }                                                                      \
    } while (0)

#define CPA_B(kt, s)                                                           \
    do {                                                                       \
        _Pragma("unroll")                                                      \
        for (int i = 0; i < 4; i++) {                                          \
            const int idx = tid + i * 512;                                     \
            const int n = idx >> 3, ku = idx & 7;                              \
            const size_t gsrc = (size_t)n * K_DIM + (kt) * 64 + ku * 8;        \
            const uint32_t d =                                                 \
                sbase + (s) * STAGE_BYTES + B_HI_OFF + n * SROWB + ku * 16;    \
            CPASYNC16(d, bH + gsrc);                                           \
            CPASYNC16(d + (B_LO_OFF - B_HI_OFF), bL + gsrc);                   \
        }                                                                      \
    } while (0)

    CPA_B(0, 0);
    CPCOMMIT();
    LDG_AH(0, 0); STS_AH(0, 0);
    LDG_AH(0, 1); STS_AH(0, 1);
    CPWAIT0();
    __syncthreads();

    const int a_row = (lane & 7) + ((lane >> 3) & 1) * 8;
    const int a_kb  = ((lane >> 4) & 1) * 16;
    const int b_row = (lane & 7) + ((lane >> 4) & 1) * 8;
    const int b_kb  = ((lane >> 3) & 1) * 16;

    for (int kt = 0; kt < NCHUNK; kt++) {
        const int s = kt & 1;
        const bool more = (kt + 1 < NCHUNK);
        if (more) {
            CPA_B(kt + 1, s ^ 1);
            CPCOMMIT();
            LDG_AH(kt + 1, 0);
        }

        const uint32_t stg = sbase + s * STAGE_BYTES;
#pragma unroll
        for (int kk = 0; kk < 2; kk++) {
            uint32_t ah[2][4];
#pragma unroll
            for (int mi = 0; mi < 2; mi++) {
                const uint32_t aaddr =
                    stg + (wm * 32 + mi * 16 + a_row) * SROWB + kk * 32 + a_kb;
                ldsm_x4(ah[mi][0], ah[mi][1], ah[mi][2], ah[mi][3], aaddr);
            }
#pragma unroll
            for (int np = 0; np < 4; np++) {
                const uint32_t baddr = stg + B_HI_OFF +
                    (wn * 64 + np * 16 + b_row) * SROWB + kk * 32 + b_kb;
                uint32_t bh0, bh1, bh2, bh3, bl0, bl1, bl2, bl3;
                ldsm_x4(bh0, bh1, bh2, bh3, baddr);
                ldsm_x4(bl0, bl1, bl2, bl3, baddr + (B_LO_OFF - B_HI_OFF));
#pragma unroll
                for (int mi = 0; mi < 2; mi++) {
                    mma_f16(acc[mi][np * 2],     ah[mi], bh0, bh1);
                    mma_f16(acc[mi][np * 2 + 1], ah[mi], bh2, bh3);
                }
#pragma unroll
                for (int mi = 0; mi < 2; mi++) {
                    mma_f16(acc[mi][np * 2],     ah[mi], bl0, bl1);
                    mma_f16(acc[mi][np * 2 + 1], ah[mi], bl2, bl3);
                }
            }
        }
        if (more) {
            STS_AH(s ^ 1, 0);
            LDG_AH(kt + 1, 1);
        }
#pragma unroll
        for (int kk = 2; kk < 4; kk++) {
            uint32_t ah[2][4];
#pragma unroll
            for (int mi = 0; mi < 2; mi++) {
                const uint32_t aaddr =
                    stg + (wm * 32 + mi * 16 + a_row) * SROWB + kk * 32 + a_kb;
                ldsm_x4(ah[mi][0], ah[mi][1], ah[mi][2], ah[mi][3], aaddr);
            }
#pragma unroll
            for (int np = 0; np < 4; np++) {
                const uint32_t baddr = stg + B_HI_OFF +
                    (wn * 64 + np * 16 + b_row) * SROWB + kk * 32 + b_kb;
                uint32_t bh0, bh1, bh2, bh3, bl0, bl1, bl2, bl3;
                ldsm_x4(bh0, bh1, bh2, bh3, baddr);
                ldsm_x4(bl0, bl1, bl2, bl3, baddr + (B_LO_OFF - B_HI_OFF));
#pragma unroll
                for (int mi = 0; mi < 2; mi++) {
                    mma_f16(acc[mi][np * 2],     ah[mi], bh0, bh1);
                    mma_f16(acc[mi][np * 2 + 1], ah[mi], bh2, bh3);
                }
#pragma unroll
                for (int mi = 0; mi < 2; mi++) {
                    mma_f16(acc[mi][np * 2],     ah[mi], bl0, bl1);
                    mma_f16(acc[mi][np * 2 + 1], ah[mi], bl2, bl3);
                }
            }
        }
        if (more) {
            STS_AH(s ^ 1, 1);
            CPWAIT0();
        }
        __syncthreads();
    }
#undef LDG_AH
#undef STS_AH
#undef CPA_B

#pragma unroll
    for (int mi = 0; mi < 2; mi++)
#pragma unroll
        for (int ni = 0; ni < 8; ni++) {
            const int row = m0 + wm * 32 + mi * 16 + (lane >> 2);
            const int col = n0 + wn * 64 + ni * 8 + (lane & 3) * 2;
            float* p = g_xg + (size_t)row * N_DIM + col;
            float2 v0, v1;
            v0.x = acc[mi][ni][0]; v0.y = acc[mi][ni][1];
            v1.x = acc[mi][ni][2]; v1.y = acc[mi][ni][3];
            *(float2*)p = v0;
            *(float2*)(p + 8 * N_DIM) = v1;
        }
}

// ===========================================================================
// Kernel L: LSTM v5 — v3 structure, inner product via fma.rn.f32x2 (FFMA2)
//   Us: [512][68] rows 0..63; rows 64..127 packed in 32 u64 regs.
// ===========================================================================
__device__ __forceinline__ float fsig(float x) { return 1.f / (1.f + __expf(-x)); }
__device__ __forceinline__ float ftanh(float x) { return 1.f - 2.f / (__expf(2.f * x) + 1.f); }

#define USTRIDE 68
#define US_FLOATS (512 * USTRIDE)
#define SM2_FLOATS (US_FLOATS + 256 + 1024)

__global__ __launch_bounds__(512) void lstm_rec(const float* __restrict__ Uh,
                                                const float* __restrict__ bias,
                                                const float* __restrict__ Wout,
                                                const float* __restrict__ bout,
                                                float* __restrict__ out) {
    extern __shared__ float smf[];
    float* Us = smf;                 // [512][68], Uh rows 0..63 per column
    float* hs = smf + US_FLOATS;     // [2][128]
    float* zs = hs + 256;            // [2][512]

    const int tid = threadIdx.x;
    const int g   = tid;
    const int b0  = blockIdx.x * 2;

    for (int k = 0; k < 64; k++) Us[g * USTRIDE + k] = Uh[k * 512 + g];
    // Uh rows 64..127 packed as 32 f32x2 registers (consecutive k-pairs)
    unsigned long long wpk[32];
#pragma unroll
    for (int r = 0; r < 32; r++) {
        const float e = Uh[(64 + 2 * r) * 512 + g];
        const float o = Uh[(64 + 2 * r + 1) * 512 + g];
        asm("mov.b64 %0,{%1,%2};" : "=l"(wpk[r]) : "f"(e), "f"(o));
    }
    const float bg   = bias[g];
    const int  gate  = g >> 7;

    if (tid < 256) hs[tid] = 0.f;
    float c = 0.f;
    __syncthreads();

    const float* xp0 = g_xg + ((size_t)b0 * 128) * 512 + g;
    const float* xp1 = g_xg + ((size_t)(b0 + 1) * 128) * 512 + g;
    float x0 = xp0[0];
    float x1 = xp1[0];

    const ulonglong2* uv2 = (const ulonglong2*)(Us + g * USTRIDE);
    const ulonglong2* hA2 = (const ulonglong2*)hs;
    const ulonglong2* hB2 = (const ulonglong2*)(hs + 128);

    for (int t = 0; t < 128; t++) {
        unsigned long long z0a = 0ull, z0b = 0ull;   // batch0: two dep chains
        unsigned long long z1a = 0ull, z1b = 0ull;   // batch1
        // SMEM part: k = 0..63 (16 x 16B rows of u and h)
#pragma unroll
        for (int q = 0; q < 16; q++) {
            const ulonglong2 u = uv2[q];
            const ulonglong2 a = hA2[q];
            const ulonglong2 b = hB2[q];
            ffma2(z0a, u.x, a.x); ffma2(z0b, u.y, a.y);
            ffma2(z1a, u.x, b.x); ffma2(z1b, u.y, b.y);
        }
        // register part: k = 64..127
#pragma unroll
        for (int q = 0; q < 16; q++) {
            const ulonglong2 a = hA2[16 + q];
            const ulonglong2 b = hB2[16 + q];
            ffma2(z0a, wpk[2 * q], a.x); ffma2(z0b, wpk[2 * q + 1], a.y);
            ffma2(z1a, wpk[2 * q], b.x); ffma2(z1b, wpk[2 * q + 1], b.y);
        }
        float z0 = x0 + bg + f2_sum(z0a) + f2_sum(z0b);
        float z1 = x1 + bg + f2_sum(z1a) + f2_sum(z1b);
        if (t + 1 < 128) {
            x0 = xp0[(t + 1) * 512];
            x1 = xp1[(t + 1) * 512];
        }

        float a0, a1;
        if (gate == 2) { a0 = ftanh(z0); a1 = ftanh(z1); }
        else           { a0 = fsig(z0);  a1 = fsig(z1);  }
        zs[g]       = a0;
        zs[512 + g] = a1;
        __syncthreads();

        if (tid < 256) {
            const int bl = tid >> 7;
            const int jj = tid & 127;
            const float* zb = zs + bl * 512;
            const float ig = zb[jj];
            const float fg = zb[128 + jj];
            const float gg = zb[256 + jj];
            const float og = zb[384 + jj];
            c = fg * c + ig * gg;
            hs[bl * 128 + jj] = og * ftanh(c);
        }
        __syncthreads();
    }

    if (tid < 256) {
        const int bl = tid >> 7;
        const int jj = tid & 127;
        const float h = hs[bl * 128 + jj];
        float p0 = h * Wout[jj * 2 + 0];
        float p1 = h * Wout[jj * 2 + 1];
#pragma unroll
        for (int off = 16; off > 0; off >>= 1) {
            p0 += __shfl_down_sync(0xffffffffu, p0, off);
            p1 += __shfl_down_sync(0xffffffffu, p1, off);
        }
        if ((tid & 31) == 0) {
            const int w = tid >> 5;
            zs[w * 2 + 0] = p0;
            zs[w * 2 + 1] = p1;
        }
    }
    __syncthreads();
    if (tid < 2) {
        float s0 = bout[0], s1 = bout[1];
#pragma unroll
        for (int w = 0; w < 4; w++) {
            s0 += zs[(tid * 4 + w) * 2 + 0];
            s1 += zs[(tid * 4 + w) * 2 + 1];
        }
        out[(b0 + tid) * 2 + 0] = s0;
        out[(b0 + tid) * 2 + 1] = s1;
    }
}

// ===========================================================================
extern "C" void kernel_launch(void* const* d_in, const int* in_sizes, int n_in,
                              void* d_out, int out_size) {
    const float* x    = (const float*)d_in[0];
    const float* Wi   = (const float*)d_in[1];
    const float* Uh   = (const float*)d_in[2];
    const float* b    = (const float*)d_in[3];
    const float* Wout = (const float*)d_in[4];
    const float* bout = (const float*)d_in[5];
    float* out = (float*)d_out;

    dim3 gp(K_DIM / 32, N_DIM / 32);
    prep_w<<<gp, dim3(32, 32)>>>(Wi);

    cudaFuncSetAttribute(gemm_hmma, cudaFuncAttributeMaxDynamicSharedMemorySize,
                         GEMM_SMEM);
    dim3 gg(N_DIM / 256, M_DIM / 128);          // (2, 256)
    gemm_hmma<<<gg, 512, GEMM_SMEM>>>(x);

    const size_t smem2 = SM2_FLOATS * sizeof(float);
    cudaFuncSetAttribute(lstm_rec, cudaFuncAttributeMaxDynamicSharedMemorySize,
                         (int)smem2);
    lstm_rec<<<128, 512, smem2>>>(Uh, b, Wout, bout, out);
}

// round 11
// speedup vs baseline: 1.9885x; 1.3324x over previous
#include <cuda_runtime.h>
#include <cuda_fp16.h>
#include <cstdint>
#include <cstddef>

// ---------------------------------------------------------------------------
// LSTM_87351044866551  (Round 11 = R10 + ONE change: GEMM 1-term fp16)
//   P: transpose Wi -> g_wh fp16 [N=512][K=2048]
//   G: xg = x16 @ W16, HMMA fp16 single-term; 512 thr, warp 32x64, K-chunk 64
//   L: LSTM recurrence v5 (exact R10 version)
//   Accuracy: x-quant (~2.6e-4) + W-quant (~2.6e-4, independent) ⇒ ~3.5-4.5e-4
// ---------------------------------------------------------------------------

#define M_DIM 32768
#define N_DIM 512
#define K_DIM 2048

__device__ float g_xg[(size_t)M_DIM * N_DIM];            // 64 MB scratch
__device__ __align__(256) __half g_wh[(size_t)N_DIM * K_DIM];

// ===========================================================================
// helpers (base ISA only — tcgen05 not assemblable on this harness)
// ===========================================================================
__device__ __forceinline__ uint32_t smem_u32(const void* p) {
    uint32_t a;
    asm("{ .reg .u64 t; cvta.to.shared.u64 t, %1; cvt.u32.u64 %0, t; }"
        : "=r"(a) : "l"(p));
    return a;
}
__device__ __forceinline__ void ldsm_x4(uint32_t& r0, uint32_t& r1,
                                        uint32_t& r2, uint32_t& r3,
                                        uint32_t addr) {
    asm volatile("ldmatrix.sync.aligned.m8n8.x4.shared.b16 {%0,%1,%2,%3},[%4];"
                 : "=r"(r0), "=r"(r1), "=r"(r2), "=r"(r3) : "r"(addr));
}
__device__ __forceinline__ void mma_f16(float* d, const uint32_t* a,
                                        uint32_t b0, uint32_t b1) {
    asm volatile(
        "mma.sync.aligned.m16n8k16.row.col.f32.f16.f16.f32 "
        "{%0,%1,%2,%3},{%4,%5,%6,%7},{%8,%9},{%0,%1,%2,%3};"
        : "+f"(d[0]), "+f"(d[1]), "+f"(d[2]), "+f"(d[3])
        : "r"(a[0]), "r"(a[1]), "r"(a[2]), "r"(a[3]), "r"(b0), "r"(b1));
}
#define CPASYNC16(dst, src) \
    asm volatile("cp.async.cg.shared.global [%0],[%1],16;" :: "r"(dst), "l"(src))
#define CPCOMMIT() asm volatile("cp.async.commit_group;" ::: "memory")
#define CPWAIT0()  asm volatile("cp.async.wait_group 0;" ::: "memory")

// packed dual-fp32 FMA: d = a*b + d (lanewise) — FFMA2
__device__ __forceinline__ void ffma2(unsigned long long& d,
                                      unsigned long long a,
                                      unsigned long long b) {
    asm("fma.rn.f32x2 %0, %1, %2, %0;" : "+l"(d) : "l"(a), "l"(b));
}
__device__ __forceinline__ float f2_sum(unsigned long long d) {
    float lo, hi;
    asm("mov.b64 {%0,%1}, %2;" : "=f"(lo), "=f"(hi) : "l"(d));
    return lo + hi;
}

// ===========================================================================
// Kernel P: Wh[n][k] = fp16(Wi[k][n])
// ===========================================================================
__global__ __launch_bounds__(1024) void prep_w(const float* __restrict__ Wi) {
    __shared__ float t[32][33];
    const int k = blockIdx.x * 32 + threadIdx.y;
    const int n = blockIdx.y * 32 + threadIdx.x;
    t[threadIdx.y][threadIdx.x] = Wi[(size_t)k * N_DIM + n];
    __syncthreads();
    const int n2 = blockIdx.y * 32 + threadIdx.y;
    const int k2 = blockIdx.x * 32 + threadIdx.x;
    g_wh[(size_t)n2 * K_DIM + k2] = __float2half_rn(t[threadIdx.x][threadIdx.y]);
}

// ===========================================================================
// Kernel G: HMMA fp16 GEMM (1 term), CTA 128x256, 512 thr, warp 32x64,
// K-chunk 64, 2-stage. Stage: A@0 (128x144), B@18432 (256x144) = 55296 B.
// ===========================================================================
#define SROWB 144
#define B_OFF 18432
#define STAGE_BYTES 55296
#define GEMM_SMEM (2 * STAGE_BYTES)   // 110592
#define NCHUNK 32                     // K / 64

__global__ __launch_bounds__(512, 1) void gemm_hmma(const float* __restrict__ x) {
    extern __shared__ __half smb[];
    const uint32_t sbase = smem_u32(smb);
    const int tid  = threadIdx.x;
    const int lane = tid & 31;
    const int w    = tid >> 5;
    const int wm   = w & 3;          // 4 M-warps of 32 rows
    const int wn   = w >> 2;         // 4 N-warps of 64 cols
    const int m0   = blockIdx.y * 128;
    const int n0   = blockIdx.x * 256;

    float acc[2][8][4];
#pragma unroll
    for (int a = 0; a < 2; a++)
#pragma unroll
        for (int b = 0; b < 8; b++)
#pragma unroll
            for (int c = 0; c < 4; c++) acc[a][b][c] = 0.f;

    const float* xA = x + (size_t)m0 * K_DIM;
    const __half* bW = g_wh + (size_t)n0 * K_DIM;

    float4 av[2];

    // A half-load: 1024 float4 (rows 64*h .. 64*h+63), 2 per thread
#define LDG_AH(kt, h)                                                          \
    do {                                                                       \
        _Pragma("unroll")                                                      \
        for (int i = 0; i < 2; i++) {                                          \
            const int idx = tid + i * 512 + (h) * 1024;                        \
            const int r = idx >> 4, f4 = idx & 15;                             \
            av[i] = *(const float4*)(xA + (size_t)r * K_DIM + (kt) * 64 + f4 * 4); \
        }                                                                      \
    } while (0)

#define STS_AH(s, h)                                                           \
    do {                                                                       \
        _Pragma("unroll")                                                      \
        for (int i = 0; i < 2; i++) {                                          \
            const int idx = tid + i * 512 + (h) * 1024;                        \
            const int r = idx >> 4, f4 = idx & 15;                             \
            const float4 v = av[i];                                            \
            __half2 p01, p23;                                                  \
            p01.x = __float2half_rn(v.x); p01.y = __float2half_rn(v.y);        \
            p23.x = __float2half_rn(v.z); p23.y = __float2half_rn(v.w);        \
            uint2 hp;                                                          \
            hp.x = *(uint32_t*)&p01; hp.y = *(uint32_t*)&p23;                  \
            *(uint2*)((char*)smb + (s) * STAGE_BYTES + r * SROWB + f4 * 8) = hp; \
        }                                                                      \
    } while (0)

    // B: 2048 16B units per chunk -> 4 per thread
#define CPA_B(kt, s)                                                           \
    do {                                                                       \
        _Pragma("unroll")                                                      \
        for (int i = 0; i < 4; i++) {                                          \
            const int idx = tid + i * 512;                                     \
            const int n = idx >> 3, ku = idx & 7;                              \
            const size_t gsrc = (size_t)n * K_DIM + (kt) * 64 + ku * 8;        \
            const uint32_t d =                                                 \
                sbase + (s) * STAGE_BYTES + B_OFF + n * SROWB + ku * 16;       \
            CPASYNC16(d, bW + gsrc);                                           \
        }                                                                      \
    } while (0)

    // prologue: chunk 0 into stage 0
    CPA_B(0, 0);
    CPCOMMIT();
    LDG_AH(0, 0); STS_AH(0, 0);
    LDG_AH(0, 1); STS_AH(0, 1);
    CPWAIT0();
    __syncthreads();

    const int a_row = (lane & 7) + ((lane >> 3) & 1) * 8;
    const int a_kb  = ((lane >> 4) & 1) * 16;
    const int b_row = (lane & 7) + ((lane >> 4) & 1) * 8;
    const int b_kb  = ((lane >> 3) & 1) * 16;

    for (int kt = 0; kt < NCHUNK; kt++) {
        const int s = kt & 1;
        const bool more = (kt + 1 < NCHUNK);
        if (more) {
            CPA_B(kt + 1, s ^ 1);
            CPCOMMIT();
            LDG_AH(kt + 1, 0);
        }

        const uint32_t stg = sbase + s * STAGE_BYTES;
        // ---- first half: kk = 0,1 ----
#pragma unroll
        for (int kk = 0; kk < 2; kk++) {
            uint32_t ah[2][4];
#pragma unroll
            for (int mi = 0; mi < 2; mi++) {
                const uint32_t aaddr =
                    stg + (wm * 32 + mi * 16 + a_row) * SROWB + kk * 32 + a_kb;
                ldsm_x4(ah[mi][0], ah[mi][1], ah[mi][2], ah[mi][3], aaddr);
            }
#pragma unroll
            for (int np = 0; np < 4; np++) {
                const uint32_t baddr = stg + B_OFF +
                    (wn * 64 + np * 16 + b_row) * SROWB + kk * 32 + b_kb;
                uint32_t b0, b1, b2, b3;
                ldsm_x4(b0, b1, b2, b3, baddr);
#pragma unroll
                for (int mi = 0; mi < 2; mi++) {
                    mma_f16(acc[mi][np * 2],     ah[mi], b0, b1);
                    mma_f16(acc[mi][np * 2 + 1], ah[mi], b2, b3);
                }
            }
        }
        if (more) {
            STS_AH(s ^ 1, 0);
            LDG_AH(kt + 1, 1);
        }
        // ---- second half: kk = 2,3 ----
#pragma unroll
        for (int kk = 2; kk < 4; kk++) {
            uint32_t ah[2][4];
#pragma unroll
            for (int mi = 0; mi < 2; mi++) {
                const uint32_t aaddr =
                    stg + (wm * 32 + mi * 16 + a_row) * SROWB + kk * 32 + a_kb;
                ldsm_x4(ah[mi][0], ah[mi][1], ah[mi][2], ah[mi][3], aaddr);
            }
#pragma unroll
            for (int np = 0; np < 4; np++) {
                const uint32_t baddr = stg + B_OFF +
                    (wn * 64 + np * 16 + b_row) * SROWB + kk * 32 + b_kb;
                uint32_t b0, b1, b2, b3;
                ldsm_x4(b0, b1, b2, b3, baddr);
#pragma unroll
                for (int mi = 0; mi < 2; mi++) {
                    mma_f16(acc[mi][np * 2],     ah[mi], b0, b1);
                    mma_f16(acc[mi][np * 2 + 1], ah[mi], b2, b3);
                }
            }
        }
        if (more) {
            STS_AH(s ^ 1, 1);
            CPWAIT0();
        }
        __syncthreads();
    }
#undef LDG_AH
#undef STS_AH
#undef CPA_B

    // epilogue
#pragma unroll
    for (int mi = 0; mi < 2; mi++)
#pragma unroll
        for (int ni = 0; ni < 8; ni++) {
            const int row = m0 + wm * 32 + mi * 16 + (lane >> 2);
            const int col = n0 + wn * 64 + ni * 8 + (lane & 3) * 2;
            float* p = g_xg + (size_t)row * N_DIM + col;
            float2 v0, v1;
            v0.x = acc[mi][ni][0]; v0.y = acc[mi][ni][1];
            v1.x = acc[mi][ni][2]; v1.y = acc[mi][ni][3];
            *(float2*)p = v0;
            *(float2*)(p + 8 * N_DIM) = v1;
        }
}

// ===========================================================================
// Kernel L: LSTM v5 (exact R10 version — FFMA2 inner product)
// ===========================================================================
__device__ __forceinline__ float fsig(float x) { return 1.f / (1.f + __expf(-x)); }
__device__ __forceinline__ float ftanh(float x) { return 1.f - 2.f / (__expf(2.f * x) + 1.f); }

#define USTRIDE 68
#define US_FLOATS (512 * USTRIDE)
#define SM2_FLOATS (US_FLOATS + 256 + 1024)

__global__ __launch_bounds__(512) void lstm_rec(const float* __restrict__ Uh,
                                                const float* __restrict__ bias,
                                                const float* __restrict__ Wout,
                                                const float* __restrict__ bout,
                                                float* __restrict__ out) {
    extern __shared__ float smf[];
    float* Us = smf;                 // [512][68], Uh rows 0..63 per column
    float* hs = smf + US_FLOATS;     // [2][128]
    float* zs = hs + 256;            // [2][512]

    const int tid = threadIdx.x;
    const int g   = tid;
    const int b0  = blockIdx.x * 2;

    for (int k = 0; k < 64; k++) Us[g * USTRIDE + k] = Uh[k * 512 + g];
    unsigned long long wpk[32];
#pragma unroll
    for (int r = 0; r < 32; r++) {
        const float e = Uh[(64 + 2 * r) * 512 + g];
        const float o = Uh[(64 + 2 * r + 1) * 512 + g];
        asm("mov.b64 %0,{%1,%2};" : "=l"(wpk[r]) : "f"(e), "f"(o));
    }
    const float bg   = bias[g];
    const int  gate  = g >> 7;

    if (tid < 256) hs[tid] = 0.f;
    float c = 0.f;
    __syncthreads();

    const float* xp0 = g_xg + ((size_t)b0 * 128) * 512 + g;
    const float* xp1 = g_xg + ((size_t)(b0 + 1) * 128) * 512 + g;
    float x0 = xp0[0];
    float x1 = xp1[0];

    const ulonglong2* uv2 = (const ulonglong2*)(Us + g * USTRIDE);
    const ulonglong2* hA2 = (const ulonglong2*)hs;
    const ulonglong2* hB2 = (const ulonglong2*)(hs + 128);

    for (int t = 0; t < 128; t++) {
        unsigned long long z0a = 0ull, z0b = 0ull;
        unsigned long long z1a = 0ull, z1b = 0ull;
#pragma unroll
        for (int q = 0; q < 16; q++) {
            const ulonglong2 u = uv2[q];
            const ulonglong2 a = hA2[q];
            const ulonglong2 b = hB2[q];
            ffma2(z0a, u.x, a.x); ffma2(z0b, u.y, a.y);
            ffma2(z1a, u.x, b.x); ffma2(z1b, u.y, b.y);
        }
#pragma unroll
        for (int q = 0; q < 16; q++) {
            const ulonglong2 a = hA2[16 + q];
            const ulonglong2 b = hB2[16 + q];
            ffma2(z0a, wpk[2 * q], a.x); ffma2(z0b, wpk[2 * q + 1], a.y);
            ffma2(z1a, wpk[2 * q], b.x); ffma2(z1b, wpk[2 * q + 1], b.y);
        }
        float z0 = x0 + bg + f2_sum(z0a) + f2_sum(z0b);
        float z1 = x1 + bg + f2_sum(z1a) + f2_sum(z1b);
        if (t + 1 < 128) {
            x0 = xp0[(t + 1) * 512];
            x1 = xp1[(t + 1) * 512];
        }

        float a0, a1;
        if (gate == 2) { a0 = ftanh(z0); a1 = ftanh(z1); }
        else           { a0 = fsig(z0);  a1 = fsig(z1);  }
        zs[g]       = a0;
        zs[512 + g] = a1;
        __syncthreads();

        if (tid < 256) {
            const int bl = tid >> 7;
            const int jj = tid & 127;
            const float* zb = zs + bl * 512;
            const float ig = zb[jj];
            const float fg = zb[128 + jj];
            const float gg = zb[256 + jj];
            const float og = zb[384 + jj];
            c = fg * c + ig * gg;
            hs[bl * 128 + jj] = og * ftanh(c);
        }
        __syncthreads();
    }

    if (tid < 256) {
        const int bl = tid >> 7;
        const int jj = tid & 127;
        const float h = hs[bl * 128 + jj];
        float p0 = h * Wout[jj * 2 + 0];
        float p1 = h * Wout[jj * 2 + 1];
#pragma unroll
        for (int off = 16; off > 0; off >>= 1) {
            p0 += __shfl_down_sync(0xffffffffu, p0, off);
            p1 += __shfl_down_sync(0xffffffffu, p1, off);
        }
        if ((tid & 31) == 0) {
            const int w = tid >> 5;
            zs[w * 2 + 0] = p0;
            zs[w * 2 + 1] = p1;
        }
    }
    __syncthreads();
    if (tid < 2) {
        float s0 = bout[0], s1 = bout[1];
#pragma unroll
        for (int w = 0; w < 4; w++) {
            s0 += zs[(tid * 4 + w) * 2 + 0];
            s1 += zs[(tid * 4 + w) * 2 + 1];
        }
        out[(b0 + tid) * 2 + 0] = s0;
        out[(b0 + tid) * 2 + 1] = s1;
    }
}

// ===========================================================================
extern "C" void kernel_launch(void* const* d_in, const int* in_sizes, int n_in,
                              void* d_out, int out_size) {
    const float* x    = (const float*)d_in[0];
    const float* Wi   = (const float*)d_in[1];
    const float* Uh   = (const float*)d_in[2];
    const float* b    = (const float*)d_in[3];
    const float* Wout = (const float*)d_in[4];
    const float* bout = (const float*)d_in[5];
    float* out = (float*)d_out;

    dim3 gp(K_DIM / 32, N_DIM / 32);
    prep_w<<<gp, dim3(32, 32)>>>(Wi);

    cudaFuncSetAttribute(gemm_hmma, cudaFuncAttributeMaxDynamicSharedMemorySize,
                         GEMM_SMEM);
    dim3 gg(N_DIM / 256, M_DIM / 128);          // (2, 256)
    gemm_hmma<<<gg, 512, GEMM_SMEM>>>(x);

    const size_t smem2 = SM2_FLOATS * sizeof(float);
    cudaFuncSetAttribute(lstm_rec, cudaFuncAttributeMaxDynamicSharedMemorySize,
                         (int)smem2);
    lstm_rec<<<128, 512, smem2>>>(Uh, b, Wout, bout, out);
}